// round 7
// baseline (speedup 1.0000x reference)
#include <cuda_runtime.h>
#include <cuda_fp16.h>
#include <cstdint>
#include <math.h>

#define NB 2
#define NS 4096
#define NE 2048
#define NH 16
#define ND 128
#define NM 1024
#define NR (NB*NS)   // 8192 rows

// ---- scratch (device globals; no allocation allowed) ----
__device__ __half g_normed[NR*NE];  // 32 MiB
__device__ __half g_wqeff[NE*NE];   // 8 MiB
__device__ __half g_q[NR*NE];       // 32 MiB
__device__ __half g_kh[NH*NM*ND];   // 4 MiB  [h*M+m][d]
__device__ __half g_vt[NH*ND*NM];   // 4 MiB  [h][d][m]  (transposed)
__device__ float  g_attn[NR*NE];    // 64 MiB

// ============================================================
// helpers
// ============================================================
__device__ __forceinline__ uint32_t smem_u32(const void* p) {
    uint32_t a;
    asm("{ .reg .u64 t; cvta.to.shared.u64 t, %1; cvt.u32.u64 %0, t; }" : "=r"(a) : "l"(p));
    return a;
}
#define CP_ASYNC16(dst, src) \
    asm volatile("cp.async.cg.shared.global [%0], [%1], 16;" :: "r"(dst), "l"(src) : "memory")
#define CP_COMMIT() asm volatile("cp.async.commit_group;" ::: "memory")
#define CP_WAIT(n)  asm volatile("cp.async.wait_group %0;" :: "n"(n) : "memory")

__device__ __forceinline__ void mma16(float c[4], const uint32_t a[4], const uint32_t b[2]) {
    asm("mma.sync.aligned.m16n8k16.row.col.f32.f16.f16.f32 "
        "{%0,%1,%2,%3}, {%4,%5,%6,%7}, {%8,%9}, {%0,%1,%2,%3};"
        : "+f"(c[0]), "+f"(c[1]), "+f"(c[2]), "+f"(c[3])
        : "r"(a[0]), "r"(a[1]), "r"(a[2]), "r"(a[3]), "r"(b[0]), "r"(b[1]));
}
__device__ __forceinline__ void ldsm4(uint32_t r[4], uint32_t a) {
    asm volatile("ldmatrix.sync.aligned.m8n8.x4.shared.b16 {%0,%1,%2,%3}, [%4];"
                 : "=r"(r[0]), "=r"(r[1]), "=r"(r[2]), "=r"(r[3]) : "r"(a));
}
__device__ __forceinline__ uint32_t packh2(float lo, float hi) {
    __half2 h = __floats2half2_rn(lo, hi);
    return *(uint32_t*)&h;
}

// ============================================================
// RMSNorm -> half output
// ============================================================
__global__ __launch_bounds__(256) void k_rmsnorm_h(const float* __restrict__ x,
                                                   const float* __restrict__ w,
                                                   __half* __restrict__ out) {
    int row = blockIdx.x;
    int tid = threadIdx.x;
    const float4* xr = (const float4*)(x + (size_t)row * NE);
    float4 v0 = xr[tid];
    float4 v1 = xr[tid + 256];
    float ss = v0.x*v0.x + v0.y*v0.y + v0.z*v0.z + v0.w*v0.w
             + v1.x*v1.x + v1.y*v1.y + v1.z*v1.z + v1.w*v1.w;
    #pragma unroll
    for (int off = 16; off; off >>= 1) ss += __shfl_xor_sync(0xffffffffu, ss, off);
    __shared__ float red[8];
    if ((tid & 31) == 0) red[tid >> 5] = ss;
    __syncthreads();
    float tot = 0.f;
    #pragma unroll
    for (int i = 0; i < 8; ++i) tot += red[i];
    float scale = rsqrtf(tot * (1.0f / NE) + 1e-6f);
    const float4* wr = (const float4*)w;
    float4 w0 = wr[tid], w1 = wr[tid + 256];
    uint4 o;
    o.x = packh2(v0.x*scale*w0.x, v0.y*scale*w0.y);
    o.y = packh2(v0.z*scale*w0.z, v0.w*scale*w0.w);
    o.z = packh2(v1.x*scale*w1.x, v1.y*scale*w1.y);
    o.w = packh2(v1.z*scale*w1.z, v1.w*scale*w1.w);
    *(uint2*)(out + (size_t)row * NE + 4 * tid) = make_uint2(o.x, o.y);
    *(uint2*)(out + (size_t)row * NE + 1024 + 4 * tid) = make_uint2(o.z, o.w);
}

// ============================================================
// Final RMSNorm + residual -> fp32 output
// ============================================================
__global__ __launch_bounds__(256) void k_rmsnorm_f(const float* __restrict__ x,
                                                   const float* __restrict__ w,
                                                   const float* __restrict__ resid,
                                                   float* __restrict__ out) {
    int row = blockIdx.x;
    int tid = threadIdx.x;
    const float4* xr = (const float4*)(x + (size_t)row * NE);
    float4 v0 = xr[tid];
    float4 v1 = xr[tid + 256];
    float ss = v0.x*v0.x + v0.y*v0.y + v0.z*v0.z + v0.w*v0.w
             + v1.x*v1.x + v1.y*v1.y + v1.z*v1.z + v1.w*v1.w;
    #pragma unroll
    for (int off = 16; off; off >>= 1) ss += __shfl_xor_sync(0xffffffffu, ss, off);
    __shared__ float red[8];
    if ((tid & 31) == 0) red[tid >> 5] = ss;
    __syncthreads();
    float tot = 0.f;
    #pragma unroll
    for (int i = 0; i < 8; ++i) tot += red[i];
    float scale = rsqrtf(tot * (1.0f / NE) + 1e-6f);
    const float4* wr = (const float4*)w;
    float4 w0 = wr[tid], w1 = wr[tid + 256];
    const float4* rr = (const float4*)(resid + (size_t)row * NE);
    float4 r0 = rr[tid], r1 = rr[tid + 256];
    float4 o0, o1;
    o0.x = v0.x*scale*w0.x + r0.x; o0.y = v0.y*scale*w0.y + r0.y;
    o0.z = v0.z*scale*w0.z + r0.z; o0.w = v0.w*scale*w0.w + r0.w;
    o1.x = v1.x*scale*w1.x + r1.x; o1.y = v1.y*scale*w1.y + r1.y;
    o1.z = v1.z*scale*w1.z + r1.z; o1.w = v1.w*scale*w1.w + r1.w;
    float4* orow = (float4*)(out + (size_t)row * NE);
    orow[tid] = o0;
    orow[tid + 256] = o1;
}

// ============================================================
// Wq_eff[o,e] = sigmoid(beta) * sum_d' W_q[d,d'] * W_in[h*128+d', e]  -> half
// ============================================================
__global__ __launch_bounds__(256) void k_wqeff(const float* __restrict__ W_in,
                                               const float* __restrict__ W_q,
                                               const float* __restrict__ beta) {
    int e = blockIdx.x * 16 + threadIdx.x;
    int o = blockIdx.y * 16 + threadIdx.y;
    int h = o >> 7;
    int d = o & 127;
    float b = 1.0f / (1.0f + expf(-beta[0]));
    const float* wq = W_q + (size_t)d * ND;
    const float* wi = W_in + ((size_t)h * ND) * NE + e;
    float acc = 0.f;
    #pragma unroll 8
    for (int dp = 0; dp < ND; ++dp)
        acc += wq[dp] * wi[(size_t)dp * NE];
    g_wqeff[(size_t)o * NE + e] = __float2half_rn(acc * b);
}

// ============================================================
// K/V projections (fused, z=0 -> K [hm][d], z=1 -> V transposed [h][d][m]).
// ============================================================
__global__ __launch_bounds__(256) void k_gemm_kv(const float* __restrict__ A,
                                                 const float* __restrict__ Wk,
                                                 const float* __restrict__ Wv) {
    __shared__ float As[16][132];
    __shared__ float Bs[16][132];
    const float* Bm = blockIdx.z ? Wv : Wk;
    int tid = threadIdx.x;
    int tx = tid & 15, ty = tid >> 4;
    int m0 = blockIdx.y << 7;
    int lr = tid >> 2;
    int lc = (tid & 3) << 2;
    const float* Ab = A + (size_t)(m0 + lr) * ND + lc;
    const float* Bb = Bm + (size_t)lr * ND + lc;

    float acc[8][8];
    #pragma unroll
    for (int i = 0; i < 8; ++i)
        #pragma unroll
        for (int j = 0; j < 8; ++j) acc[i][j] = 0.f;

    for (int k0 = 0; k0 < ND; k0 += 16) {
        float4 a0 = *(const float4*)(Ab + k0);
        float4 a1 = *(const float4*)(Ab + (size_t)64 * ND + k0);
        float4 b0 = *(const float4*)(Bb + k0);
        float4 b1 = *(const float4*)(Bb + (size_t)64 * ND + k0);
        __syncthreads();
        As[lc+0][lr] = a0.x; As[lc+1][lr] = a0.y; As[lc+2][lr] = a0.z; As[lc+3][lr] = a0.w;
        As[lc+0][lr+64] = a1.x; As[lc+1][lr+64] = a1.y; As[lc+2][lr+64] = a1.z; As[lc+3][lr+64] = a1.w;
        Bs[lc+0][lr] = b0.x; Bs[lc+1][lr] = b0.y; Bs[lc+2][lr] = b0.z; Bs[lc+3][lr] = b0.w;
        Bs[lc+0][lr+64] = b1.x; Bs[lc+1][lr+64] = b1.y; Bs[lc+2][lr+64] = b1.z; Bs[lc+3][lr+64] = b1.w;
        __syncthreads();
        #pragma unroll
        for (int kk = 0; kk < 16; ++kk) {
            float4 af0 = *(const float4*)&As[kk][ty << 3];
            float4 af1 = *(const float4*)&As[kk][(ty << 3) + 4];
            float4 bf0 = *(const float4*)&Bs[kk][tx << 3];
            float4 bf1 = *(const float4*)&Bs[kk][(tx << 3) + 4];
            float a[8] = {af0.x, af0.y, af0.z, af0.w, af1.x, af1.y, af1.z, af1.w};
            float bb[8] = {bf0.x, bf0.y, bf0.z, bf0.w, bf1.x, bf1.y, bf1.z, bf1.w};
            #pragma unroll
            for (int i = 0; i < 8; ++i)
                #pragma unroll
                for (int j = 0; j < 8; ++j)
                    acc[i][j] += a[i] * bb[j];
        }
    }
    if (blockIdx.z == 0) {
        #pragma unroll
        for (int i = 0; i < 8; ++i) {
            int row = m0 + (ty << 3) + i;
            uint4 o;
            o.x = packh2(acc[i][0], acc[i][1]);
            o.y = packh2(acc[i][2], acc[i][3]);
            o.z = packh2(acc[i][4], acc[i][5]);
            o.w = packh2(acc[i][6], acc[i][7]);
            *(uint4*)(g_kh + (size_t)row * ND + (tx << 3)) = o;
        }
    } else {
        int h = m0 >> 10;
        int ml0 = (m0 & 1023) + (ty << 3);
        #pragma unroll
        for (int j = 0; j < 8; ++j) {
            int d = (tx << 3) + j;
            uint4 o;
            o.x = packh2(acc[0][j], acc[1][j]);
            o.y = packh2(acc[2][j], acc[3][j]);
            o.z = packh2(acc[4][j], acc[5][j]);
            o.w = packh2(acc[6][j], acc[7][j]);
            *(uint4*)(g_vt + (size_t)h * (ND * NM) + (size_t)d * NM + ml0) = o;
        }
    }
}

// ============================================================
// fp16 mma GEMM, ldmatrix, 3-stage cp.async pipeline, 1 sync/iter.
// C[M,N] = A[M,K] @ B[N,K]^T. CTA 128x128, BK=64, 8 warps (2x4), warp 64x32.
// ============================================================
#define AST 72
__global__ __launch_bounds__(256) void k_gemm_mma(const __half* __restrict__ A,
                                                  const __half* __restrict__ B,
                                                  __half* __restrict__ C,
                                                  int M, int N, int K) {
    extern __shared__ __half smh[];
    __half* As = smh;                   // [3][128*AST]
    __half* Bs = smh + 3 * 128 * AST;   // [3][128*AST]
    const int tid = threadIdx.x;
    const int wid = tid >> 5, lid = tid & 31;
    const int g = lid >> 2, tig = lid & 3;
    const int q = lid >> 3, rr = lid & 7;
    const int qrow = (q & 1) * 8 + rr, qcolA = (q >> 1) * 8;   // A ldsm pattern
    const int brow = (q >> 1) * 8 + rr, bcol = (q & 1) * 8;    // B ldsm pattern
    const int wm = wid & 1, wn = wid >> 1;
    const int m0 = blockIdx.y << 7, n0 = blockIdx.x << 7;

    float c[4][4][4];
    #pragma unroll
    for (int mt = 0; mt < 4; ++mt)
        #pragma unroll
        for (int nt = 0; nt < 4; ++nt)
            #pragma unroll
            for (int r = 0; r < 4; ++r) c[mt][nt][r] = 0.f;

    const int NKC = K >> 6;
    // prologue: stages 0 and 1
    #pragma unroll
    for (int s = 0; s < 2; ++s) {
        uint32_t ab = smem_u32(As + s * 128 * AST);
        uint32_t bb = smem_u32(Bs + s * 128 * AST);
        int k0 = s << 6;
        #pragma unroll
        for (int it = 0; it < 4; ++it) {
            int idx = it * 256 + tid;
            int row = idx >> 3, kq = (idx & 7) << 3;
            CP_ASYNC16(ab + (row * AST + kq) * 2, A + (size_t)(m0 + row) * K + k0 + kq);
            CP_ASYNC16(bb + (row * AST + kq) * 2, B + (size_t)(n0 + row) * K + k0 + kq);
        }
        CP_COMMIT();
    }

    int cur = 0;
    for (int kc = 0; kc < NKC; ++kc) {
        CP_WAIT(1);          // stage cur ready
        __syncthreads();     // prev-iter readers done before reusing slot
        if (kc + 2 < NKC) {
            int s = (cur + 2) % 3;
            int k0 = (kc + 2) << 6;
            uint32_t ab = smem_u32(As + s * 128 * AST);
            uint32_t bb = smem_u32(Bs + s * 128 * AST);
            #pragma unroll
            for (int it = 0; it < 4; ++it) {
                int idx = it * 256 + tid;
                int row = idx >> 3, kq = (idx & 7) << 3;
                CP_ASYNC16(ab + (row * AST + kq) * 2, A + (size_t)(m0 + row) * K + k0 + kq);
                CP_ASYNC16(bb + (row * AST + kq) * 2, B + (size_t)(n0 + row) * K + k0 + kq);
            }
            CP_COMMIT();
        } else {
            CP_COMMIT();     // keep group accounting uniform
        }
        uint32_t abase = smem_u32(As + cur * 128 * AST);
        uint32_t bbase = smem_u32(Bs + cur * 128 * AST);
        #pragma unroll
        for (int kk = 0; kk < 4; ++kk) {
            uint32_t a[4][4], bf[4][2];
            #pragma unroll
            for (int mt = 0; mt < 4; ++mt)
                ldsm4(a[mt], abase + ((wm * 64 + mt * 16 + qrow) * AST + kk * 16 + qcolA) * 2);
            #pragma unroll
            for (int p = 0; p < 2; ++p) {
                uint32_t t[4];
                ldsm4(t, bbase + ((wn * 32 + p * 16 + brow) * AST + kk * 16 + bcol) * 2);
                bf[2*p][0] = t[0]; bf[2*p][1] = t[1];
                bf[2*p+1][0] = t[2]; bf[2*p+1][1] = t[3];
            }
            #pragma unroll
            for (int mt = 0; mt < 4; ++mt)
                #pragma unroll
                for (int nt = 0; nt < 4; ++nt)
                    mma16(c[mt][nt], a[mt], bf[nt]);
        }
        cur = (cur + 1) % 3;
    }

    #pragma unroll
    for (int mt = 0; mt < 4; ++mt) {
        int r0 = m0 + wm * 64 + mt * 16 + g;
        #pragma unroll
        for (int nt = 0; nt < 4; ++nt) {
            int cn = n0 + wn * 32 + nt * 8 + 2 * tig;
            *(uint32_t*)(C + (size_t)r0 * N + cn) = packh2(c[mt][nt][0], c[mt][nt][1]);
            *(uint32_t*)(C + (size_t)(r0 + 8) * N + cn) = packh2(c[mt][nt][2], c[mt][nt][3]);
        }
    }
}

// ============================================================
// FA2-style fp16 mma attention: 512 threads / 16 warps, CTA = 256 q-rows
// of one (b,h). Halves K/V L2 traffic vs 128-row CTAs. P in registers,
// K/V double-buffered, max-free softmax.
// smem: Q[256*PST] + 2xK[128*PST] + 2xV[128*PST] = 208896 B.
// ============================================================
#define PST 136
__global__ __launch_bounds__(512, 1) void k_attn_mma() {
    extern __shared__ __half smh[];
    __half* Qs = smh;                     // 256*PST
    __half* Ks0 = Qs + 256 * PST;         // 2 buffers
    __half* Vs0 = Ks0 + 2 * 128 * PST;    // 2 buffers

    const int tid = threadIdx.x;
    const int wid = tid >> 5, lid = tid & 31;
    const int g = lid >> 2, tig = lid & 3;
    const int q = lid >> 3, rr = lid & 7;
    const int qrow = (q & 1) * 8 + rr, qcolA = (q >> 1) * 8;
    const int brow = (q >> 1) * 8 + rr, bcol = (q & 1) * 8;
    const int rw = wid * 16;              // warp's q-row base (0..240)
    const int bh = blockIdx.y;
    const int b = bh >> 4, h = bh & 15;
    const int s0 = blockIdx.x << 8;       // 256 rows per CTA

    const __half* qb = g_q + ((size_t)(b * NS + s0)) * NE + h * ND;
    const __half* kb0 = g_kh + (size_t)h * NM * ND;
    const __half* vb0 = g_vt + (size_t)h * ND * NM;

    // prologue: Q (256x128) + chunk-0 K/V (128x128 each)
    {
        uint32_t qa = smem_u32(Qs);
        #pragma unroll
        for (int it = 0; it < 8; ++it) {
            int cix = it * 512 + tid;
            int row = cix >> 4, colh = (cix & 15) << 3;
            CP_ASYNC16(qa + (row * PST + colh) * 2, qb + (size_t)row * NE + colh);
        }
        uint32_t ka = smem_u32(Ks0), va = smem_u32(Vs0);
        #pragma unroll
        for (int it = 0; it < 4; ++it) {
            int cix = it * 512 + tid;
            int row = cix >> 4, colh = (cix & 15) << 3;
            CP_ASYNC16(ka + (row * PST + colh) * 2, kb0 + (size_t)row * ND + colh);
            CP_ASYNC16(va + (row * PST + colh) * 2, vb0 + (size_t)row * NM + colh);
        }
        CP_COMMIT();
    }

    float oc[16][4];
    #pragma unroll
    for (int nt = 0; nt < 16; ++nt)
        #pragma unroll
        for (int r = 0; r < 4; ++r) oc[nt][r] = 0.f;
    float lrun0 = 0.f, lrun1 = 0.f;

    const uint32_t qbase = smem_u32(Qs);

    for (int ch = 0; ch < 8; ++ch) {
        CP_WAIT(0);
        __syncthreads();
        int cur = ch & 1;
        if (ch + 1 < 8) {
            int m0n = (ch + 1) << 7;
            uint32_t ka = smem_u32(Ks0 + (cur ^ 1) * 128 * PST);
            uint32_t va = smem_u32(Vs0 + (cur ^ 1) * 128 * PST);
            #pragma unroll
            for (int it = 0; it < 4; ++it) {
                int cix = it * 512 + tid;
                int row = cix >> 4, colh = (cix & 15) << 3;
                CP_ASYNC16(ka + (row * PST + colh) * 2, kb0 + (size_t)(m0n + row) * ND + colh);
                CP_ASYNC16(va + (row * PST + colh) * 2, vb0 + (size_t)row * NM + m0n + colh);
            }
            CP_COMMIT();
        }
        uint32_t kbase = smem_u32(Ks0 + cur * 128 * PST);
        uint32_t vbase = smem_u32(Vs0 + cur * 128 * PST);

        // two halves of 64 keys each
        #pragma unroll
        for (int hf = 0; hf < 2; ++hf) {
            // phase 1: S[16 x 64] = Q(rows rw..rw+15) @ K[hf]^T
            float sc[8][4];
            #pragma unroll
            for (int nt = 0; nt < 8; ++nt)
                #pragma unroll
                for (int r = 0; r < 4; ++r) sc[nt][r] = 0.f;
            #pragma unroll
            for (int kk = 0; kk < 8; ++kk) {
                uint32_t a[4], bf[8][2];
                ldsm4(a, qbase + ((rw + qrow) * PST + kk * 16 + qcolA) * 2);
                #pragma unroll
                for (int p = 0; p < 4; ++p) {
                    uint32_t t[4];
                    ldsm4(t, kbase + ((hf * 64 + p * 16 + brow) * PST + kk * 16 + bcol) * 2);
                    bf[2*p][0] = t[0]; bf[2*p][1] = t[1];
                    bf[2*p+1][0] = t[2]; bf[2*p+1][1] = t[3];
                }
                #pragma unroll
                for (int nt = 0; nt < 8; ++nt)
                    mma16(sc[nt], a, bf[nt]);
            }

            // exp in registers; pack into phase-2 A fragments; row sums
            uint32_t pa[4][4];
            float rs0 = 0.f, rs1 = 0.f;
            #pragma unroll
            for (int nt = 0; nt < 8; ++nt) {
                float e0 = __expf(sc[nt][0]);
                float e1 = __expf(sc[nt][1]);
                float e2 = __expf(sc[nt][2]);
                float e3 = __expf(sc[nt][3]);
                rs0 += e0 + e1;
                rs1 += e2 + e3;
                int k2 = nt >> 1;
                if ((nt & 1) == 0) {
                    pa[k2][0] = packh2(e0, e1);
                    pa[k2][1] = packh2(e2, e3);
                } else {
                    pa[k2][2] = packh2(e0, e1);
                    pa[k2][3] = packh2(e2, e3);
                }
            }
            rs0 += __shfl_xor_sync(0xffffffffu, rs0, 1);
            rs0 += __shfl_xor_sync(0xffffffffu, rs0, 2);
            rs1 += __shfl_xor_sync(0xffffffffu, rs1, 1);
            rs1 += __shfl_xor_sync(0xffffffffu, rs1, 2);
            lrun0 += rs0;
            lrun1 += rs1;

            // phase 2: O[16 x 128] += P[16 x 64] @ V[hf]  (B from Vt[d][m])
            #pragma unroll
            for (int k2 = 0; k2 < 4; ++k2) {
                uint32_t bf[16][2];
                #pragma unroll
                for (int p = 0; p < 8; ++p) {
                    uint32_t t[4];
                    ldsm4(t, vbase + ((p * 16 + brow) * PST + hf * 64 + k2 * 16 + bcol) * 2);
                    bf[2*p][0] = t[0]; bf[2*p][1] = t[1];
                    bf[2*p+1][0] = t[2]; bf[2*p+1][1] = t[3];
                }
                #pragma unroll
                for (int nt = 0; nt < 16; ++nt)
                    mma16(oc[nt], pa[k2], bf[nt]);
            }
        }
    }

    // epilogue: normalize by row sums, write fp32
    float inv0 = 1.0f / lrun0;
    float inv1 = 1.0f / lrun1;
    float* ob0 = g_attn + ((size_t)(b * NS + s0 + rw + g)) * NE + h * ND;
    float* ob1 = g_attn + ((size_t)(b * NS + s0 + rw + g + 8)) * NE + h * ND;
    #pragma unroll
    for (int nt = 0; nt < 16; ++nt) {
        int dn = nt * 8 + 2 * tig;
        *(float2*)(ob0 + dn) = make_float2(oc[nt][0] * inv0, oc[nt][1] * inv0);
        *(float2*)(ob1 + dn) = make_float2(oc[nt][2] * inv1, oc[nt][3] * inv1);
    }
}

// ============================================================
// launch
// ============================================================
extern "C" void kernel_launch(void* const* d_in, const int* in_sizes, int n_in,
                              void* d_out, int out_size) {
    const float* query  = (const float*)d_in[0];
    const float* W_in   = (const float*)d_in[1];
    const float* W_q    = (const float*)d_in[2];
    const float* W_k    = (const float*)d_in[3];
    const float* W_v    = (const float*)d_in[4];
    const float* stored = (const float*)d_in[5];
    const float* nw_q   = (const float*)d_in[6];
    const float* nw_r   = (const float*)d_in[7];
    const float* beta   = (const float*)d_in[8];
    float* out = (float*)d_out;

    __half *p_normed, *p_wqeff, *p_q;
    float *p_attn;
    cudaGetSymbolAddress((void**)&p_normed, g_normed);
    cudaGetSymbolAddress((void**)&p_wqeff,  g_wqeff);
    cudaGetSymbolAddress((void**)&p_q,      g_q);
    cudaGetSymbolAddress((void**)&p_attn,   g_attn);

    const int gemm_smem = 3 * 2 * 128 * AST * 2;             // 110592 B
    const int attn_smem = (256 + 4 * 128) * PST * 2;         // 208896 B
    cudaFuncSetAttribute(k_gemm_mma, cudaFuncAttributeMaxDynamicSharedMemorySize, gemm_smem);
    cudaFuncSetAttribute(k_attn_mma, cudaFuncAttributeMaxDynamicSharedMemorySize, attn_smem);

    k_rmsnorm_h<<<NR, 256>>>(query, nw_q, p_normed);
    k_wqeff<<<dim3(NE / 16, NE / 16), dim3(16, 16)>>>(W_in, W_q, beta);
    k_gemm_kv<<<dim3(1, (NH * NM) / 128, 2), 256>>>(stored, W_k, W_v);
    k_gemm_mma<<<dim3(NE / 128, NR / 128), 256, gemm_smem>>>(p_normed, p_wqeff, p_q, NR, NE, NE);
    k_attn_mma<<<dim3(NS / 256, NB * NH), 512, attn_smem>>>();
    k_rmsnorm_f<<<NR, 256>>>(p_attn, nw_r, query, out);
}

// round 8
// speedup vs baseline: 1.0142x; 1.0142x over previous
#include <cuda_runtime.h>
#include <cuda_fp16.h>
#include <cstdint>
#include <math.h>

#define NB 2
#define NS 4096
#define NE 2048
#define NH 16
#define ND 128
#define NM 1024
#define NR (NB*NS)   // 8192 rows

// ---- scratch (device globals; no allocation allowed) ----
__device__ __half g_normed[NR*NE];  // 32 MiB
__device__ __half g_wqeff[NE*NE];   // 8 MiB
__device__ __half g_q[NR*NE];       // 32 MiB
__device__ __half g_kh[NH*NM*ND];   // 4 MiB  [h*M+m][d]
__device__ __half g_vt[NH*ND*NM];   // 4 MiB  [h][d][m]  (transposed)
__device__ float  g_attn[NR*NE];    // 64 MiB

// ============================================================
// helpers
// ============================================================
__device__ __forceinline__ uint32_t smem_u32(const void* p) {
    uint32_t a;
    asm("{ .reg .u64 t; cvta.to.shared.u64 t, %1; cvt.u32.u64 %0, t; }" : "=r"(a) : "l"(p));
    return a;
}
#define CP_ASYNC16(dst, src) \
    asm volatile("cp.async.cg.shared.global [%0], [%1], 16;" :: "r"(dst), "l"(src) : "memory")
#define CP_COMMIT() asm volatile("cp.async.commit_group;" ::: "memory")
#define CP_WAIT(n)  asm volatile("cp.async.wait_group %0;" :: "n"(n) : "memory")

__device__ __forceinline__ void mma16(float c[4], const uint32_t a[4], const uint32_t b[2]) {
    asm("mma.sync.aligned.m16n8k16.row.col.f32.f16.f16.f32 "
        "{%0,%1,%2,%3}, {%4,%5,%6,%7}, {%8,%9}, {%0,%1,%2,%3};"
        : "+f"(c[0]), "+f"(c[1]), "+f"(c[2]), "+f"(c[3])
        : "r"(a[0]), "r"(a[1]), "r"(a[2]), "r"(a[3]), "r"(b[0]), "r"(b[1]));
}
__device__ __forceinline__ void ldsm4(uint32_t r[4], uint32_t a) {
    asm volatile("ldmatrix.sync.aligned.m8n8.x4.shared.b16 {%0,%1,%2,%3}, [%4];"
                 : "=r"(r[0]), "=r"(r[1]), "=r"(r[2]), "=r"(r[3]) : "r"(a));
}
__device__ __forceinline__ uint32_t packh2(float lo, float hi) {
    __half2 h = __floats2half2_rn(lo, hi);
    return *(uint32_t*)&h;
}

// ============================================================
// RMSNorm -> half output
// ============================================================
__global__ __launch_bounds__(256) void k_rmsnorm_h(const float* __restrict__ x,
                                                   const float* __restrict__ w,
                                                   __half* __restrict__ out) {
    int row = blockIdx.x;
    int tid = threadIdx.x;
    const float4* xr = (const float4*)(x + (size_t)row * NE);
    float4 v0 = xr[tid];
    float4 v1 = xr[tid + 256];
    float ss = v0.x*v0.x + v0.y*v0.y + v0.z*v0.z + v0.w*v0.w
             + v1.x*v1.x + v1.y*v1.y + v1.z*v1.z + v1.w*v1.w;
    #pragma unroll
    for (int off = 16; off; off >>= 1) ss += __shfl_xor_sync(0xffffffffu, ss, off);
    __shared__ float red[8];
    if ((tid & 31) == 0) red[tid >> 5] = ss;
    __syncthreads();
    float tot = 0.f;
    #pragma unroll
    for (int i = 0; i < 8; ++i) tot += red[i];
    float scale = rsqrtf(tot * (1.0f / NE) + 1e-6f);
    const float4* wr = (const float4*)w;
    float4 w0 = wr[tid], w1 = wr[tid + 256];
    uint4 o;
    o.x = packh2(v0.x*scale*w0.x, v0.y*scale*w0.y);
    o.y = packh2(v0.z*scale*w0.z, v0.w*scale*w0.w);
    o.z = packh2(v1.x*scale*w1.x, v1.y*scale*w1.y);
    o.w = packh2(v1.z*scale*w1.z, v1.w*scale*w1.w);
    *(uint2*)(out + (size_t)row * NE + 4 * tid) = make_uint2(o.x, o.y);
    *(uint2*)(out + (size_t)row * NE + 1024 + 4 * tid) = make_uint2(o.z, o.w);
}

// ============================================================
// Final RMSNorm + residual -> fp32 output
// ============================================================
__global__ __launch_bounds__(256) void k_rmsnorm_f(const float* __restrict__ x,
                                                   const float* __restrict__ w,
                                                   const float* __restrict__ resid,
                                                   float* __restrict__ out) {
    int row = blockIdx.x;
    int tid = threadIdx.x;
    const float4* xr = (const float4*)(x + (size_t)row * NE);
    float4 v0 = xr[tid];
    float4 v1 = xr[tid + 256];
    float ss = v0.x*v0.x + v0.y*v0.y + v0.z*v0.z + v0.w*v0.w
             + v1.x*v1.x + v1.y*v1.y + v1.z*v1.z + v1.w*v1.w;
    #pragma unroll
    for (int off = 16; off; off >>= 1) ss += __shfl_xor_sync(0xffffffffu, ss, off);
    __shared__ float red[8];
    if ((tid & 31) == 0) red[tid >> 5] = ss;
    __syncthreads();
    float tot = 0.f;
    #pragma unroll
    for (int i = 0; i < 8; ++i) tot += red[i];
    float scale = rsqrtf(tot * (1.0f / NE) + 1e-6f);
    const float4* wr = (const float4*)w;
    float4 w0 = wr[tid], w1 = wr[tid + 256];
    const float4* rr = (const float4*)(resid + (size_t)row * NE);
    float4 r0 = rr[tid], r1 = rr[tid + 256];
    float4 o0, o1;
    o0.x = v0.x*scale*w0.x + r0.x; o0.y = v0.y*scale*w0.y + r0.y;
    o0.z = v0.z*scale*w0.z + r0.z; o0.w = v0.w*scale*w0.w + r0.w;
    o1.x = v1.x*scale*w1.x + r1.x; o1.y = v1.y*scale*w1.y + r1.y;
    o1.z = v1.z*scale*w1.z + r1.z; o1.w = v1.w*scale*w1.w + r1.w;
    float4* orow = (float4*)(out + (size_t)row * NE);
    orow[tid] = o0;
    orow[tid + 256] = o1;
}

// ============================================================
// Wq_eff[o,e] = sigmoid(beta) * sum_d' W_q[d,d'] * W_in[h*128+d', e]  -> half
// ============================================================
__global__ __launch_bounds__(256) void k_wqeff(const float* __restrict__ W_in,
                                               const float* __restrict__ W_q,
                                               const float* __restrict__ beta) {
    int e = blockIdx.x * 16 + threadIdx.x;
    int o = blockIdx.y * 16 + threadIdx.y;
    int h = o >> 7;
    int d = o & 127;
    float b = 1.0f / (1.0f + expf(-beta[0]));
    const float* wq = W_q + (size_t)d * ND;
    const float* wi = W_in + ((size_t)h * ND) * NE + e;
    float acc = 0.f;
    #pragma unroll 8
    for (int dp = 0; dp < ND; ++dp)
        acc += wq[dp] * wi[(size_t)dp * NE];
    g_wqeff[(size_t)o * NE + e] = __float2half_rn(acc * b);
}

// ============================================================
// K/V projections (fused, z=0 -> K [hm][d], z=1 -> V transposed [h][d][m]).
// ============================================================
__global__ __launch_bounds__(256) void k_gemm_kv(const float* __restrict__ A,
                                                 const float* __restrict__ Wk,
                                                 const float* __restrict__ Wv) {
    __shared__ float As[16][132];
    __shared__ float Bs[16][132];
    const float* Bm = blockIdx.z ? Wv : Wk;
    int tid = threadIdx.x;
    int tx = tid & 15, ty = tid >> 4;
    int m0 = blockIdx.y << 7;
    int lr = tid >> 2;
    int lc = (tid & 3) << 2;
    const float* Ab = A + (size_t)(m0 + lr) * ND + lc;
    const float* Bb = Bm + (size_t)lr * ND + lc;

    float acc[8][8];
    #pragma unroll
    for (int i = 0; i < 8; ++i)
        #pragma unroll
        for (int j = 0; j < 8; ++j) acc[i][j] = 0.f;

    for (int k0 = 0; k0 < ND; k0 += 16) {
        float4 a0 = *(const float4*)(Ab + k0);
        float4 a1 = *(const float4*)(Ab + (size_t)64 * ND + k0);
        float4 b0 = *(const float4*)(Bb + k0);
        float4 b1 = *(const float4*)(Bb + (size_t)64 * ND + k0);
        __syncthreads();
        As[lc+0][lr] = a0.x; As[lc+1][lr] = a0.y; As[lc+2][lr] = a0.z; As[lc+3][lr] = a0.w;
        As[lc+0][lr+64] = a1.x; As[lc+1][lr+64] = a1.y; As[lc+2][lr+64] = a1.z; As[lc+3][lr+64] = a1.w;
        Bs[lc+0][lr] = b0.x; Bs[lc+1][lr] = b0.y; Bs[lc+2][lr] = b0.z; Bs[lc+3][lr] = b0.w;
        Bs[lc+0][lr+64] = b1.x; Bs[lc+1][lr+64] = b1.y; Bs[lc+2][lr+64] = b1.z; Bs[lc+3][lr+64] = b1.w;
        __syncthreads();
        #pragma unroll
        for (int kk = 0; kk < 16; ++kk) {
            float4 af0 = *(const float4*)&As[kk][ty << 3];
            float4 af1 = *(const float4*)&As[kk][(ty << 3) + 4];
            float4 bf0 = *(const float4*)&Bs[kk][tx << 3];
            float4 bf1 = *(const float4*)&Bs[kk][(tx << 3) + 4];
            float a[8] = {af0.x, af0.y, af0.z, af0.w, af1.x, af1.y, af1.z, af1.w};
            float bb[8] = {bf0.x, bf0.y, bf0.z, bf0.w, bf1.x, bf1.y, bf1.z, bf1.w};
            #pragma unroll
            for (int i = 0; i < 8; ++i)
                #pragma unroll
                for (int j = 0; j < 8; ++j)
                    acc[i][j] += a[i] * bb[j];
        }
    }
    if (blockIdx.z == 0) {
        #pragma unroll
        for (int i = 0; i < 8; ++i) {
            int row = m0 + (ty << 3) + i;
            uint4 o;
            o.x = packh2(acc[i][0], acc[i][1]);
            o.y = packh2(acc[i][2], acc[i][3]);
            o.z = packh2(acc[i][4], acc[i][5]);
            o.w = packh2(acc[i][6], acc[i][7]);
            *(uint4*)(g_kh + (size_t)row * ND + (tx << 3)) = o;
        }
    } else {
        int h = m0 >> 10;
        int ml0 = (m0 & 1023) + (ty << 3);
        #pragma unroll
        for (int j = 0; j < 8; ++j) {
            int d = (tx << 3) + j;
            uint4 o;
            o.x = packh2(acc[0][j], acc[1][j]);
            o.y = packh2(acc[2][j], acc[3][j]);
            o.z = packh2(acc[4][j], acc[5][j]);
            o.w = packh2(acc[6][j], acc[7][j]);
            *(uint4*)(g_vt + (size_t)h * (ND * NM) + (size_t)d * NM + ml0) = o;
        }
    }
}

// ============================================================
// fp16 mma GEMM, ldmatrix, 64x64 warp tiles (4 warps, CTA 128x128),
// BK=64, 2-stage cp.async. mma:ldsm-wavefront ratio 1:1.
// ============================================================
#define AST 72
__global__ __launch_bounds__(128) void k_gemm_mma(const __half* __restrict__ A,
                                                  const __half* __restrict__ B,
                                                  __half* __restrict__ C,
                                                  int M, int N, int K) {
    extern __shared__ __half smh[];
    __half* As = smh;                   // [2][128*AST]
    __half* Bs = smh + 2 * 128 * AST;   // [2][128*AST]
    const int tid = threadIdx.x;
    const int wid = tid >> 5, lid = tid & 31;
    const int g = lid >> 2, tig = lid & 3;
    const int q = lid >> 3, rr = lid & 7;
    const int qrow = (q & 1) * 8 + rr, qcolA = (q >> 1) * 8;   // A ldsm pattern
    const int brow = (q >> 1) * 8 + rr, bcol = (q & 1) * 8;    // B ldsm pattern
    const int wm = wid & 1, wn = wid >> 1;                     // 2x2 warps, 64x64 each
    const int m0 = blockIdx.y << 7, n0 = blockIdx.x << 7;

    float c[4][8][4];
    #pragma unroll
    for (int mt = 0; mt < 4; ++mt)
        #pragma unroll
        for (int nt = 0; nt < 8; ++nt)
            #pragma unroll
            for (int r = 0; r < 4; ++r) c[mt][nt][r] = 0.f;

    const int NKC = K >> 6;
    {
        uint32_t ab = smem_u32(As), bb = smem_u32(Bs);
        #pragma unroll
        for (int it = 0; it < 8; ++it) {
            int idx = it * 128 + tid;
            int row = idx >> 3, kq = (idx & 7) << 3;
            CP_ASYNC16(ab + (row * AST + kq) * 2, A + (size_t)(m0 + row) * K + kq);
            CP_ASYNC16(bb + (row * AST + kq) * 2, B + (size_t)(n0 + row) * K + kq);
        }
        CP_COMMIT();
    }

    for (int kc = 0; kc < NKC; ++kc) {
        int cur = kc & 1;
        if (kc + 1 < NKC) {
            int nb = cur ^ 1;
            int k0 = (kc + 1) << 6;
            uint32_t ab = smem_u32(As + nb * 128 * AST);
            uint32_t bb = smem_u32(Bs + nb * 128 * AST);
            #pragma unroll
            for (int it = 0; it < 8; ++it) {
                int idx = it * 128 + tid;
                int row = idx >> 3, kq = (idx & 7) << 3;
                CP_ASYNC16(ab + (row * AST + kq) * 2, A + (size_t)(m0 + row) * K + k0 + kq);
                CP_ASYNC16(bb + (row * AST + kq) * 2, B + (size_t)(n0 + row) * K + k0 + kq);
            }
            CP_COMMIT();
            CP_WAIT(1);
        } else {
            CP_WAIT(0);
        }
        __syncthreads();
        uint32_t abase = smem_u32(As + cur * 128 * AST);
        uint32_t bbase = smem_u32(Bs + cur * 128 * AST);
        #pragma unroll
        for (int kk = 0; kk < 4; ++kk) {
            uint32_t a[4][4], bf[8][2];
            #pragma unroll
            for (int mt = 0; mt < 4; ++mt)
                ldsm4(a[mt], abase + ((wm * 64 + mt * 16 + qrow) * AST + kk * 16 + qcolA) * 2);
            #pragma unroll
            for (int p = 0; p < 4; ++p) {
                uint32_t t[4];
                ldsm4(t, bbase + ((wn * 64 + p * 16 + brow) * AST + kk * 16 + bcol) * 2);
                bf[2*p][0] = t[0]; bf[2*p][1] = t[1];
                bf[2*p+1][0] = t[2]; bf[2*p+1][1] = t[3];
            }
            #pragma unroll
            for (int mt = 0; mt < 4; ++mt)
                #pragma unroll
                for (int nt = 0; nt < 8; ++nt)
                    mma16(c[mt][nt], a[mt], bf[nt]);
        }
        __syncthreads();
    }

    #pragma unroll
    for (int mt = 0; mt < 4; ++mt) {
        int r0 = m0 + wm * 64 + mt * 16 + g;
        #pragma unroll
        for (int nt = 0; nt < 8; ++nt) {
            int cn = n0 + wn * 64 + nt * 8 + 2 * tig;
            *(uint32_t*)(C + (size_t)r0 * N + cn) = packh2(c[mt][nt][0], c[mt][nt][1]);
            *(uint32_t*)(C + (size_t)(r0 + 8) * N + cn) = packh2(c[mt][nt][2], c[mt][nt][3]);
        }
    }
}

// ============================================================
// FA2-style fp16 mma attention (R6 config): 256 thr / 8 warps,
// CTA = 128 q-rows of one (b,h), 8 chunks of 128 keys, P in registers,
// K/V double-buffered, max-free softmax.
// ============================================================
#define PST 136
__global__ __launch_bounds__(256) void k_attn_mma() {
    extern __shared__ __half smh[];
    __half* Qs = smh;                     // 128*PST
    __half* Ks0 = Qs + 128 * PST;         // 2 buffers
    __half* Vs0 = Ks0 + 2 * 128 * PST;    // 2 buffers

    const int tid = threadIdx.x;
    const int wid = tid >> 5, lid = tid & 31;
    const int g = lid >> 2, tig = lid & 3;
    const int q = lid >> 3, rr = lid & 7;
    const int qrow = (q & 1) * 8 + rr, qcolA = (q >> 1) * 8;
    const int brow = (q >> 1) * 8 + rr, bcol = (q & 1) * 8;
    const int rw = wid * 16;              // warp's q-row base
    const int bh = blockIdx.y;
    const int b = bh >> 4, h = bh & 15;
    const int s0 = blockIdx.x << 7;

    const __half* qb = g_q + ((size_t)(b * NS + s0)) * NE + h * ND;
    const __half* kb0 = g_kh + (size_t)h * NM * ND;
    const __half* vb0 = g_vt + (size_t)h * ND * NM;

    // prologue: Q + chunk-0 K/V (full coverage)
    {
        uint32_t qa = smem_u32(Qs);
        uint32_t ka = smem_u32(Ks0), va = smem_u32(Vs0);
        #pragma unroll
        for (int it = 0; it < 8; ++it) {
            int cix = it * 256 + tid;
            int row = cix >> 4, colh = (cix & 15) << 3;
            CP_ASYNC16(qa + (row * PST + colh) * 2, qb + (size_t)row * NE + colh);
            CP_ASYNC16(ka + (row * PST + colh) * 2, kb0 + (size_t)row * ND + colh);
            CP_ASYNC16(va + (row * PST + colh) * 2, vb0 + (size_t)row * NM + colh);
        }
        CP_COMMIT();
    }

    float oc[16][4];
    #pragma unroll
    for (int nt = 0; nt < 16; ++nt)
        #pragma unroll
        for (int r = 0; r < 4; ++r) oc[nt][r] = 0.f;
    float lrun0 = 0.f, lrun1 = 0.f;

    const uint32_t qbase = smem_u32(Qs);

    for (int ch = 0; ch < 8; ++ch) {
        CP_WAIT(0);
        __syncthreads();
        int cur = ch & 1;
        if (ch + 1 < 8) {
            int m0n = (ch + 1) << 7;
            uint32_t ka = smem_u32(Ks0 + (cur ^ 1) * 128 * PST);
            uint32_t va = smem_u32(Vs0 + (cur ^ 1) * 128 * PST);
            #pragma unroll
            for (int it = 0; it < 8; ++it) {
                int cix = it * 256 + tid;
                int row = cix >> 4, colh = (cix & 15) << 3;
                CP_ASYNC16(ka + (row * PST + colh) * 2, kb0 + (size_t)(m0n + row) * ND + colh);
                CP_ASYNC16(va + (row * PST + colh) * 2, vb0 + (size_t)row * NM + m0n + colh);
            }
            CP_COMMIT();
        }
        uint32_t kbase = smem_u32(Ks0 + cur * 128 * PST);
        uint32_t vbase = smem_u32(Vs0 + cur * 128 * PST);

        // two halves of 64 keys each
        #pragma unroll
        for (int hf = 0; hf < 2; ++hf) {
            // phase 1: S[16 x 64] = Q(rows rw..rw+15) @ K[hf]^T
            float sc[8][4];
            #pragma unroll
            for (int nt = 0; nt < 8; ++nt)
                #pragma unroll
                for (int r = 0; r < 4; ++r) sc[nt][r] = 0.f;
            #pragma unroll
            for (int kk = 0; kk < 8; ++kk) {
                uint32_t a[4], bf[8][2];
                ldsm4(a, qbase + ((rw + qrow) * PST + kk * 16 + qcolA) * 2);
                #pragma unroll
                for (int p = 0; p < 4; ++p) {
                    uint32_t t[4];
                    ldsm4(t, kbase + ((hf * 64 + p * 16 + brow) * PST + kk * 16 + bcol) * 2);
                    bf[2*p][0] = t[0]; bf[2*p][1] = t[1];
                    bf[2*p+1][0] = t[2]; bf[2*p+1][1] = t[3];
                }
                #pragma unroll
                for (int nt = 0; nt < 8; ++nt)
                    mma16(sc[nt], a, bf[nt]);
            }

            // exp in registers; pack into phase-2 A fragments; row sums
            uint32_t pa[4][4];
            float rs0 = 0.f, rs1 = 0.f;
            #pragma unroll
            for (int nt = 0; nt < 8; ++nt) {
                float e0 = __expf(sc[nt][0]);
                float e1 = __expf(sc[nt][1]);
                float e2 = __expf(sc[nt][2]);
                float e3 = __expf(sc[nt][3]);
                rs0 += e0 + e1;
                rs1 += e2 + e3;
                int k2 = nt >> 1;
                if ((nt & 1) == 0) {
                    pa[k2][0] = packh2(e0, e1);
                    pa[k2][1] = packh2(e2, e3);
                } else {
                    pa[k2][2] = packh2(e0, e1);
                    pa[k2][3] = packh2(e2, e3);
                }
            }
            rs0 += __shfl_xor_sync(0xffffffffu, rs0, 1);
            rs0 += __shfl_xor_sync(0xffffffffu, rs0, 2);
            rs1 += __shfl_xor_sync(0xffffffffu, rs1, 1);
            rs1 += __shfl_xor_sync(0xffffffffu, rs1, 2);
            lrun0 += rs0;
            lrun1 += rs1;

            // phase 2: O[16 x 128] += P[16 x 64] @ V[hf]  (B from Vt[d][m])
            #pragma unroll
            for (int k2 = 0; k2 < 4; ++k2) {
                uint32_t bf[16][2];
                #pragma unroll
                for (int p = 0; p < 8; ++p) {
                    uint32_t t[4];
                    ldsm4(t, vbase + ((p * 16 + brow) * PST + hf * 64 + k2 * 16 + bcol) * 2);
                    bf[2*p][0] = t[0]; bf[2*p][1] = t[1];
                    bf[2*p+1][0] = t[2]; bf[2*p+1][1] = t[3];
                }
                #pragma unroll
                for (int nt = 0; nt < 16; ++nt)
                    mma16(oc[nt], pa[k2], bf[nt]);
            }
        }
    }

    // epilogue: normalize by row sums, write fp32
    float inv0 = 1.0f / lrun0;
    float inv1 = 1.0f / lrun1;
    float* ob0 = g_attn + ((size_t)(b * NS + s0 + rw + g)) * NE + h * ND;
    float* ob1 = g_attn + ((size_t)(b * NS + s0 + rw + g + 8)) * NE + h * ND;
    #pragma unroll
    for (int nt = 0; nt < 16; ++nt) {
        int dn = nt * 8 + 2 * tig;
        *(float2*)(ob0 + dn) = make_float2(oc[nt][0] * inv0, oc[nt][1] * inv0);
        *(float2*)(ob1 + dn) = make_float2(oc[nt][2] * inv1, oc[nt][3] * inv1);
    }
}

// ============================================================
// launch
// ============================================================
extern "C" void kernel_launch(void* const* d_in, const int* in_sizes, int n_in,
                              void* d_out, int out_size) {
    const float* query  = (const float*)d_in[0];
    const float* W_in   = (const float*)d_in[1];
    const float* W_q    = (const float*)d_in[2];
    const float* W_k    = (const float*)d_in[3];
    const float* W_v    = (const float*)d_in[4];
    const float* stored = (const float*)d_in[5];
    const float* nw_q   = (const float*)d_in[6];
    const float* nw_r   = (const float*)d_in[7];
    const float* beta   = (const float*)d_in[8];
    float* out = (float*)d_out;

    __half *p_normed, *p_wqeff, *p_q;
    float *p_attn;
    cudaGetSymbolAddress((void**)&p_normed, g_normed);
    cudaGetSymbolAddress((void**)&p_wqeff,  g_wqeff);
    cudaGetSymbolAddress((void**)&p_q,      g_q);
    cudaGetSymbolAddress((void**)&p_attn,   g_attn);

    const int gemm_smem = 2 * 2 * 128 * AST * 2;   // 73728 B
    const int attn_smem = 5 * 128 * PST * 2;       // 174080 B
    cudaFuncSetAttribute(k_gemm_mma, cudaFuncAttributeMaxDynamicSharedMemorySize, gemm_smem);
    cudaFuncSetAttribute(k_attn_mma, cudaFuncAttributeMaxDynamicSharedMemorySize, attn_smem);

    k_rmsnorm_h<<<NR, 256>>>(query, nw_q, p_normed);
    k_wqeff<<<dim3(NE / 16, NE / 16), dim3(16, 16)>>>(W_in, W_q, beta);
    k_gemm_kv<<<dim3(1, (NH * NM) / 128, 2), 256>>>(stored, W_k, W_v);
    k_gemm_mma<<<dim3(NE / 128, NR / 128), 128, gemm_smem>>>(p_normed, p_wqeff, p_q, NR, NE, NE);
    k_attn_mma<<<dim3(NS / 128, NB * NH), 256, attn_smem>>>();
    k_rmsnorm_f<<<NR, 256>>>(p_attn, nw_r, query, out);
}